// round 2
// baseline (speedup 1.0000x reference)
#include <cuda_runtime.h>
#include <math.h>

#define Zb 2
#define Nn 2048
#define DM 1024
#define Hh 16
#define DKk 64
#define Tt (Zb*Nn)   // 4096

// ---------------- scratch (no allocations allowed) ----------------
__device__ __align__(16) float g_Q[Zb*Hh*Nn*DKk];
__device__ __align__(16) float g_K[Zb*Hh*Nn*DKk];
__device__ __align__(16) float g_V[Zb*Hh*Nn*DKk];
__device__ __align__(16) float g_ctx[Tt*DM];
__device__ int g_mask[Tt];

// ---------------- mask dtype detection + expansion ----------------
// The reference mask is jax bool; on-disk dtype could be bool(1B), int32, or
// float32. Detect from byte patterns over the first 4096 bytes (safe for all
// three layouts), deterministically, then expand to g_mask[Tt] ints.
__global__ void mask_kernel(const unsigned char* __restrict__ raw) {
    __shared__ int s_gt1, s_off;
    int tid = threadIdx.x;
    if (tid == 0) { s_gt1 = 0; s_off = 0; }
    __syncthreads();
    int gt1 = 0, off = 0;
    for (int i = tid; i < Tt; i += blockDim.x) {
        unsigned char b = raw[i];
        if (b > 1) gt1 = 1;
        if (b && (i & 3)) off = 1;
    }
    if (gt1) atomicOr(&s_gt1, 1);
    if (off) atomicOr(&s_off, 1);
    __syncthreads();
    // float32 has 0x3F/0x80 bytes (>1); bool has 0/1 bytes at offsets %4!=0;
    // int32 0/1 has nonzero bytes only at offsets %4==0.
    int mode = s_gt1 ? 2 : (s_off ? 0 : 1);  // 0=bool, 1=int32, 2=float32
    for (int i = tid; i < Tt; i += blockDim.x) {
        int v;
        if (mode == 0)      v = (raw[i] != 0);
        else if (mode == 1) v = (((const int*)raw)[i] != 0);
        else                v = (((const float*)raw)[i] != 0.0f);
        g_mask[i] = v;
    }
}

// ---------------- fused QKV projection ----------------
// grid.x = Tt/64 token tiles, grid.y = 3*H (which, head). 64x64 tile, BK=16,
// 256 threads, 4x4 microtile.
__global__ __launch_bounds__(256) void qkv_kernel(
    const float* __restrict__ x,
    const float* __restrict__ qp, const float* __restrict__ kp, const float* __restrict__ vp,
    const float* __restrict__ qb, const float* __restrict__ kb, const float* __restrict__ vb)
{
    __shared__ __align__(16) float sA[64 * 20];   // [token][d] pad 20
    __shared__ __align__(16) float sB[16 * 68];   // [d][dk]   pad 68

    int tid = threadIdx.x, tx = tid & 15, ty = tid >> 4;
    int t0 = blockIdx.x * 64;
    int which = blockIdx.y / Hh, h = blockIdx.y % Hh;
    const float* W  = (which == 0 ? qp : which == 1 ? kp : vp) + h * DM * DKk;
    const float* Bi = (which == 0 ? qb : which == 1 ? kb : vb) + h * DKk;

    float acc[4][4] = {};

    for (int d0 = 0; d0 < DM; d0 += 16) {
        {   // A tile: 64 tokens x 16 dims
            int q = tid >> 2, d4 = tid & 3;
            *(float4*)&sA[q * 20 + d4 * 4] =
                *(const float4*)&x[(t0 + q) * DM + d0 + d4 * 4];
        }
        {   // B tile: 16 dims x 64 dk (row-major in W already)
            int kk = tid >> 4, c4 = tid & 15;
            *(float4*)&sB[kk * 68 + c4 * 4] =
                *(const float4*)&W[(d0 + kk) * DKk + c4 * 4];
        }
        __syncthreads();
        #pragma unroll
        for (int kk = 0; kk < 16; kk++) {
            float4 b4 = *(float4*)&sB[kk * 68 + tx * 4];
            float bb[4] = {b4.x, b4.y, b4.z, b4.w};
            float a[4];
            #pragma unroll
            for (int i = 0; i < 4; i++) a[i] = sA[(ty * 4 + i) * 20 + kk];
            #pragma unroll
            for (int i = 0; i < 4; i++)
                #pragma unroll
                for (int j = 0; j < 4; j++) acc[i][j] += a[i] * bb[j];
        }
        __syncthreads();
    }

    float* out = (which == 0 ? g_Q : which == 1 ? g_K : g_V);
    int c = tx * 4;
    #pragma unroll
    for (int i = 0; i < 4; i++) {
        int t = t0 + ty * 4 + i;
        int z = t >> 11, n = t & (Nn - 1);
        float4 o;
        o.x = acc[i][0] + Bi[c + 0];
        o.y = acc[i][1] + Bi[c + 1];
        o.z = acc[i][2] + Bi[c + 2];
        o.w = acc[i][3] + Bi[c + 3];
        *(float4*)&out[((z * Hh + h) * Nn + n) * DKk + c] = o;
    }
}

// ---------------- flash attention ----------------
// One CTA per (query-tile of 64, head, batch). Online softmax state kept in
// registers (rows owned exclusively by a 16-lane group; shuffle reductions).
#define PAD 68
#define ATTN_SMEM (4 * 64 * PAD * 4)

__global__ __launch_bounds__(256) void attn_kernel() {
    extern __shared__ __align__(16) float sm[];
    float* Qs = sm;                 // [q][d]   64xPAD
    float* Kt = sm + 64 * PAD;      // [d][key] 64xPAD (transposed)
    float* Vs = sm + 2 * 64 * PAD;  // [key][d] 64xPAD
    float* Ps = sm + 3 * 64 * PAD;  // [q][key] 64xPAD

    int tid = threadIdx.x, tx = tid & 15, ty = tid >> 4;
    int q0 = blockIdx.x * 64;
    int h = blockIdx.y, z = blockIdx.z;
    const float* Qg = g_Q + (size_t)((z * Hh + h) * Nn) * DKk;
    const float* Kg = g_K + (size_t)((z * Hh + h) * Nn) * DKk;
    const float* Vg = g_V + (size_t)((z * Hh + h) * Nn) * DKk;

    // load Q tile (64x64)
    #pragma unroll
    for (int it = 0; it < 4; it++) {
        int idx = tid + it * 256;
        int q = idx >> 4, d4 = idx & 15;
        *(float4*)&Qs[q * PAD + d4 * 4] =
            *(const float4*)&Qg[(q0 + q) * DKk + d4 * 4];
    }

    float m_i[4], l_i[4], acc[4][4];
    #pragma unroll
    for (int i = 0; i < 4; i++) {
        m_i[i] = -1e30f; l_i[i] = 0.0f;
        #pragma unroll
        for (int j = 0; j < 4; j++) acc[i][j] = 0.0f;
    }
    const float scale = 0.125f;  // 1/sqrt(64)

    for (int k0 = 0; k0 < Nn; k0 += 64) {
        __syncthreads();  // protect Kt/Vs/Ps from previous iteration readers
        #pragma unroll
        for (int it = 0; it < 4; it++) {
            int idx = tid + it * 256;
            int key = idx >> 4, d4 = idx & 15;
            float4 kv = *(const float4*)&Kg[(k0 + key) * DKk + d4 * 4];
            Kt[(d4 * 4 + 0) * PAD + key] = kv.x;
            Kt[(d4 * 4 + 1) * PAD + key] = kv.y;
            Kt[(d4 * 4 + 2) * PAD + key] = kv.z;
            Kt[(d4 * 4 + 3) * PAD + key] = kv.w;
            *(float4*)&Vs[key * PAD + d4 * 4] =
                *(const float4*)&Vg[(k0 + key) * DKk + d4 * 4];
        }
        __syncthreads();

        // S = Q K^T (64x64x64)
        float s[4][4] = {};
        #pragma unroll 16
        for (int kk = 0; kk < 64; kk++) {
            float4 b4 = *(float4*)&Kt[kk * PAD + tx * 4];
            float bb[4] = {b4.x, b4.y, b4.z, b4.w};
            float a[4];
            #pragma unroll
            for (int i = 0; i < 4; i++) a[i] = Qs[(ty * 4 + i) * PAD + kk];
            #pragma unroll
            for (int i = 0; i < 4; i++)
                #pragma unroll
                for (int j = 0; j < 4; j++) s[i][j] += a[i] * bb[j];
        }

        // mask + scale (exact -1e9 like reference)
        int kvalid[4];
        #pragma unroll
        for (int j = 0; j < 4; j++) kvalid[j] = g_mask[z * Nn + k0 + tx * 4 + j];
        #pragma unroll
        for (int i = 0; i < 4; i++)
            #pragma unroll
            for (int j = 0; j < 4; j++)
                s[i][j] = kvalid[j] ? s[i][j] * scale : -1e9f;

        // online softmax, per query row (16-lane groups share a row)
        #pragma unroll
        for (int i = 0; i < 4; i++) {
            float tm = fmaxf(fmaxf(s[i][0], s[i][1]), fmaxf(s[i][2], s[i][3]));
            #pragma unroll
            for (int off = 8; off; off >>= 1)
                tm = fmaxf(tm, __shfl_xor_sync(0xffffffffu, tm, off));
            float mnew = fmaxf(m_i[i], tm);
            float fac = __expf(m_i[i] - mnew);
            float ps = 0.0f;
            #pragma unroll
            for (int j = 0; j < 4; j++) {
                s[i][j] = __expf(s[i][j] - mnew);
                ps += s[i][j];
            }
            #pragma unroll
            for (int off = 8; off; off >>= 1)
                ps += __shfl_xor_sync(0xffffffffu, ps, off);
            l_i[i] = l_i[i] * fac + ps;
            m_i[i] = mnew;
            #pragma unroll
            for (int j = 0; j < 4; j++) acc[i][j] *= fac;
            *(float4*)&Ps[(ty * 4 + i) * PAD + tx * 4] =
                make_float4(s[i][0], s[i][1], s[i][2], s[i][3]);
        }
        __syncthreads();

        // acc += P V (64x64x64)
        #pragma unroll 16
        for (int kk = 0; kk < 64; kk++) {
            float4 b4 = *(float4*)&Vs[kk * PAD + tx * 4];
            float bb[4] = {b4.x, b4.y, b4.z, b4.w};
            float a[4];
            #pragma unroll
            for (int i = 0; i < 4; i++) a[i] = Ps[(ty * 4 + i) * PAD + kk];
            #pragma unroll
            for (int i = 0; i < 4; i++)
                #pragma unroll
                for (int j = 0; j < 4; j++) acc[i][j] += a[i] * bb[j];
        }
    }

    // epilogue: normalize, zero invalid queries, write ctx in [t][Dm] layout
    #pragma unroll
    for (int i = 0; i < 4; i++) {
        int q = q0 + ty * 4 + i;
        float inv = g_mask[z * Nn + q] ? (1.0f / l_i[i]) : 0.0f;
        float4 o = make_float4(acc[i][0] * inv, acc[i][1] * inv,
                               acc[i][2] * inv, acc[i][3] * inv);
        *(float4*)&g_ctx[(size_t)(z * Nn + q) * DM + h * DKk + tx * 4] = o;
    }
}

// ---------------- output projection: out = ctx @ Wo^T ----------------
__global__ __launch_bounds__(256) void outproj_kernel(
    const float* __restrict__ Wo, float* __restrict__ out)
{
    __shared__ __align__(16) float sA[64 * 20];
    __shared__ __align__(16) float sB[16 * 68];

    int tid = threadIdx.x, tx = tid & 15, ty = tid >> 4;
    int t0 = blockIdx.x * 64, c0 = blockIdx.y * 64;
    float acc[4][4] = {};

    for (int i0 = 0; i0 < DM; i0 += 16) {
        {
            int q = tid >> 2, d4 = tid & 3;
            *(float4*)&sA[q * 20 + d4 * 4] =
                *(const float4*)&g_ctx[(size_t)(t0 + q) * DM + i0 + d4 * 4];
        }
        {   // B[kk][c] = Wo[c0+c][i0+kk] (transpose on store)
            int c = tid >> 2, k4 = tid & 3;
            float4 w4 = *(const float4*)&Wo[(size_t)(c0 + c) * DM + i0 + k4 * 4];
            sB[(k4 * 4 + 0) * 68 + c] = w4.x;
            sB[(k4 * 4 + 1) * 68 + c] = w4.y;
            sB[(k4 * 4 + 2) * 68 + c] = w4.z;
            sB[(k4 * 4 + 3) * 68 + c] = w4.w;
        }
        __syncthreads();
        #pragma unroll
        for (int kk = 0; kk < 16; kk++) {
            float4 b4 = *(float4*)&sB[kk * 68 + tx * 4];
            float bb[4] = {b4.x, b4.y, b4.z, b4.w};
            float a[4];
            #pragma unroll
            for (int i = 0; i < 4; i++) a[i] = sA[(ty * 4 + i) * 20 + kk];
            #pragma unroll
            for (int i = 0; i < 4; i++)
                #pragma unroll
                for (int j = 0; j < 4; j++) acc[i][j] += a[i] * bb[j];
        }
        __syncthreads();
    }

    #pragma unroll
    for (int i = 0; i < 4; i++) {
        *(float4*)&out[(size_t)(t0 + ty * 4 + i) * DM + c0 + tx * 4] =
            make_float4(acc[i][0], acc[i][1], acc[i][2], acc[i][3]);
    }
}

// ---------------- launch ----------------
extern "C" void kernel_launch(void* const* d_in, const int* in_sizes, int n_in,
                              void* d_out, int out_size) {
    const float* x  = (const float*)d_in[0];
    const unsigned char* mraw = (const unsigned char*)d_in[1];
    const float* qp = (const float*)d_in[2];
    const float* kp = (const float*)d_in[3];
    const float* vp = (const float*)d_in[4];
    const float* qb = (const float*)d_in[5];
    const float* kb = (const float*)d_in[6];
    const float* vb = (const float*)d_in[7];
    const float* ow = (const float*)d_in[8];
    float* out = (float*)d_out;

    cudaFuncSetAttribute(attn_kernel,
                         cudaFuncAttributeMaxDynamicSharedMemorySize, ATTN_SMEM);

    mask_kernel<<<1, 256>>>(mraw);
    qkv_kernel<<<dim3(Tt / 64, 3 * Hh), 256>>>(x, qp, kp, vp, qb, kb, vb);
    attn_kernel<<<dim3(Nn / 64, Hh, Zb), 256, ATTN_SMEM>>>();
    outproj_kernel<<<dim3(Tt / 64, DM / 64), 256>>>(ow, out);
}

// round 3
// speedup vs baseline: 1.1519x; 1.1519x over previous
#include <cuda_runtime.h>
#include <math.h>

#define Zb 2
#define Nn 2048
#define DM 1024
#define Hh 16
#define DKk 64
#define Tt (Zb*Nn)   // 4096

// ---------------- scratch (no allocations allowed) ----------------
__device__ __align__(16) float g_Q[Zb*Hh*Nn*DKk];
__device__ __align__(16) float g_K[Zb*Hh*Nn*DKk];
__device__ __align__(16) float g_V[Zb*Hh*Nn*DKk];
__device__ __align__(16) float g_ctx[Tt*DM];
__device__ int g_mask[Tt];

// ---------------- mask dtype detection + expansion ----------------
__global__ void mask_kernel(const unsigned char* __restrict__ raw) {
    __shared__ int s_gt1, s_off;
    int tid = threadIdx.x;
    if (tid == 0) { s_gt1 = 0; s_off = 0; }
    __syncthreads();
    int gt1 = 0, off = 0;
    for (int i = tid; i < Tt; i += blockDim.x) {
        unsigned char b = raw[i];
        if (b > 1) gt1 = 1;
        if (b && (i & 3)) off = 1;
    }
    if (gt1) atomicOr(&s_gt1, 1);
    if (off) atomicOr(&s_off, 1);
    __syncthreads();
    int mode = s_gt1 ? 2 : (s_off ? 0 : 1);  // 0=bool, 1=int32, 2=float32
    for (int i = tid; i < Tt; i += blockDim.x) {
        int v;
        if (mode == 0)      v = (raw[i] != 0);
        else if (mode == 1) v = (((const int*)raw)[i] != 0);
        else                v = (((const float*)raw)[i] != 0.0f);
        g_mask[i] = v;
    }
}

// ---------------- fused QKV projection ----------------
// 128 tokens x 64 dk tile, BK=16, 256 threads, 8x4 split microtile.
// sA staged k-major so A-reads are float4 broadcasts across tx.
#define SApad 132
__global__ __launch_bounds__(256) void qkv_kernel(
    const float* __restrict__ x,
    const float* __restrict__ qp, const float* __restrict__ kp, const float* __restrict__ vp,
    const float* __restrict__ qb, const float* __restrict__ kb, const float* __restrict__ vb)
{
    __shared__ __align__(16) float sA[16 * SApad];  // [k][token]
    __shared__ __align__(16) float sB[16 * 68];     // [k][dk]

    int tid = threadIdx.x, tx = tid & 15, ty = tid >> 4;
    int t0 = blockIdx.x * 128;
    int which = blockIdx.y / Hh, h = blockIdx.y % Hh;
    const float* W  = (which == 0 ? qp : which == 1 ? kp : vp) + h * DM * DKk;
    const float* Bi = (which == 0 ? qb : which == 1 ? kb : vb) + h * DKk;

    float acc[8][4] = {};

    for (int d0 = 0; d0 < DM; d0 += 16) {
        #pragma unroll
        for (int it = 0; it < 2; it++) {  // A: 128x16 transposed into [k][tok]
            int idx = tid + it * 256;
            int tok = idx >> 2, d4 = idx & 3;
            float4 v4 = *(const float4*)&x[(t0 + tok) * DM + d0 + d4 * 4];
            sA[(d4 * 4 + 0) * SApad + tok] = v4.x;
            sA[(d4 * 4 + 1) * SApad + tok] = v4.y;
            sA[(d4 * 4 + 2) * SApad + tok] = v4.z;
            sA[(d4 * 4 + 3) * SApad + tok] = v4.w;
        }
        {   // B: 16x64
            int kk = tid >> 4, c4 = tid & 15;
            *(float4*)&sB[kk * 68 + c4 * 4] =
                *(const float4*)&W[(d0 + kk) * DKk + c4 * 4];
        }
        __syncthreads();
        #pragma unroll
        for (int kk = 0; kk < 16; kk++) {
            float4 b4 = *(float4*)&sB[kk * 68 + tx * 4];
            float bb[4] = {b4.x, b4.y, b4.z, b4.w};
            float4 a0 = *(float4*)&sA[kk * SApad + ty * 4];
            float4 a1 = *(float4*)&sA[kk * SApad + 64 + ty * 4];
            float aa[8] = {a0.x, a0.y, a0.z, a0.w, a1.x, a1.y, a1.z, a1.w};
            #pragma unroll
            for (int i = 0; i < 8; i++)
                #pragma unroll
                for (int j = 0; j < 4; j++) acc[i][j] += aa[i] * bb[j];
        }
        __syncthreads();
    }

    float* out = (which == 0 ? g_Q : which == 1 ? g_K : g_V);
    int c = tx * 4;
    float4 bias4 = make_float4(Bi[c], Bi[c + 1], Bi[c + 2], Bi[c + 3]);
    #pragma unroll
    for (int i = 0; i < 8; i++) {
        int r = (i < 4) ? (ty * 4 + i) : (64 + ty * 4 + (i - 4));
        int t = t0 + r;
        int z = t >> 11, n = t & (Nn - 1);
        float4 o = make_float4(acc[i][0] + bias4.x, acc[i][1] + bias4.y,
                               acc[i][2] + bias4.z, acc[i][3] + bias4.w);
        *(float4*)&out[((z * Hh + h) * Nn + n) * DKk + c] = o;
    }
}

// ---------------- flash attention ----------------
// 128-query x 64-key blocks, 256 threads, 8x4 micro for S and PV.
// P written transposed (Pt[key][q]) as float4 so PV A-reads are broadcasts.
#define ATTN_SMEM ((64 * SApad * 2 + 64 * 68 * 2) * 4)

__global__ __launch_bounds__(256) void attn_kernel() {
    extern __shared__ __align__(16) float sm[];
    float* Qs = sm;                          // [d][q]   64 x 132
    float* Kt = Qs + 64 * SApad;             // [d][key] 64 x 68
    float* Vs = Kt + 64 * 68;                // [key][d] 64 x 68
    float* Pt = Vs + 64 * 68;                // [key][q] 64 x 132

    int tid = threadIdx.x, tx = tid & 15, ty = tid >> 4;
    int q0 = blockIdx.x * 128;
    int h = blockIdx.y, z = blockIdx.z;
    const float* Qg = g_Q + (size_t)((z * Hh + h) * Nn) * DKk;
    const float* Kg = g_K + (size_t)((z * Hh + h) * Nn) * DKk;
    const float* Vg = g_V + (size_t)((z * Hh + h) * Nn) * DKk;

    // load Q tile (128x64) transposed into Qs[d][q]
    #pragma unroll
    for (int it = 0; it < 8; it++) {
        int idx = tid + it * 256;
        int q = idx >> 4, d4 = idx & 15;
        float4 v4 = *(const float4*)&Qg[(q0 + q) * DKk + d4 * 4];
        Qs[(d4 * 4 + 0) * SApad + q] = v4.x;
        Qs[(d4 * 4 + 1) * SApad + q] = v4.y;
        Qs[(d4 * 4 + 2) * SApad + q] = v4.z;
        Qs[(d4 * 4 + 3) * SApad + q] = v4.w;
    }

    float m_i[8], l_i[8], acc[8][4];
    #pragma unroll
    for (int i = 0; i < 8; i++) {
        m_i[i] = -1e30f; l_i[i] = 0.0f;
        #pragma unroll
        for (int j = 0; j < 4; j++) acc[i][j] = 0.0f;
    }
    const float scale = 0.125f;  // 1/sqrt(64)

    for (int k0 = 0; k0 < Nn; k0 += 64) {
        __syncthreads();  // protect Kt/Vs/Pt from previous iteration readers
        #pragma unroll
        for (int it = 0; it < 4; it++) {
            int idx = tid + it * 256;
            int key = idx >> 4, d4 = idx & 15;
            float4 kv = *(const float4*)&Kg[(k0 + key) * DKk + d4 * 4];
            Kt[(d4 * 4 + 0) * 68 + key] = kv.x;
            Kt[(d4 * 4 + 1) * 68 + key] = kv.y;
            Kt[(d4 * 4 + 2) * 68 + key] = kv.z;
            Kt[(d4 * 4 + 3) * 68 + key] = kv.w;
            *(float4*)&Vs[key * 68 + d4 * 4] =
                *(const float4*)&Vg[(k0 + key) * DKk + d4 * 4];
        }
        __syncthreads();

        // S = Q K^T : 128q x 64k over d=64
        float s[8][4] = {};
        #pragma unroll 16
        for (int kk = 0; kk < 64; kk++) {
            float4 b4 = *(float4*)&Kt[kk * 68 + tx * 4];
            float bb[4] = {b4.x, b4.y, b4.z, b4.w};
            float4 a0 = *(float4*)&Qs[kk * SApad + ty * 4];
            float4 a1 = *(float4*)&Qs[kk * SApad + 64 + ty * 4];
            float aa[8] = {a0.x, a0.y, a0.z, a0.w, a1.x, a1.y, a1.z, a1.w};
            #pragma unroll
            for (int i = 0; i < 8; i++)
                #pragma unroll
                for (int j = 0; j < 4; j++) s[i][j] += aa[i] * bb[j];
        }

        // mask + scale
        int kvalid[4];
        #pragma unroll
        for (int j = 0; j < 4; j++) kvalid[j] = g_mask[z * Nn + k0 + tx * 4 + j];
        #pragma unroll
        for (int i = 0; i < 8; i++)
            #pragma unroll
            for (int j = 0; j < 4; j++)
                s[i][j] = kvalid[j] ? s[i][j] * scale : -1e9f;

        // online softmax per query row (16-lane tx groups share a row)
        #pragma unroll
        for (int i = 0; i < 8; i++) {
            float tm = fmaxf(fmaxf(s[i][0], s[i][1]), fmaxf(s[i][2], s[i][3]));
            #pragma unroll
            for (int off = 8; off; off >>= 1)
                tm = fmaxf(tm, __shfl_xor_sync(0xffffffffu, tm, off));
            float mnew = fmaxf(m_i[i], tm);
            float fac = __expf(m_i[i] - mnew);
            float ps = 0.0f;
            #pragma unroll
            for (int j = 0; j < 4; j++) {
                s[i][j] = __expf(s[i][j] - mnew);
                ps += s[i][j];
            }
            #pragma unroll
            for (int off = 8; off; off >>= 1)
                ps += __shfl_xor_sync(0xffffffffu, ps, off);
            l_i[i] = l_i[i] * fac + ps;
            m_i[i] = mnew;
            #pragma unroll
            for (int j = 0; j < 4; j++) acc[i][j] *= fac;
        }
        // store P transposed: Pt[key][q], vectorized over the 4 rows a thread owns
        #pragma unroll
        for (int j = 0; j < 4; j++) {
            int key = tx * 4 + j;
            *(float4*)&Pt[key * SApad + ty * 4] =
                make_float4(s[0][j], s[1][j], s[2][j], s[3][j]);
            *(float4*)&Pt[key * SApad + 64 + ty * 4] =
                make_float4(s[4][j], s[5][j], s[6][j], s[7][j]);
        }
        __syncthreads();

        // acc += P V : 128q x 64d over key=64
        #pragma unroll 16
        for (int kk = 0; kk < 64; kk++) {
            float4 b4 = *(float4*)&Vs[kk * 68 + tx * 4];
            float bb[4] = {b4.x, b4.y, b4.z, b4.w};
            float4 a0 = *(float4*)&Pt[kk * SApad + ty * 4];
            float4 a1 = *(float4*)&Pt[kk * SApad + 64 + ty * 4];
            float aa[8] = {a0.x, a0.y, a0.z, a0.w, a1.x, a1.y, a1.z, a1.w};
            #pragma unroll
            for (int i = 0; i < 8; i++)
                #pragma unroll
                for (int j = 0; j < 4; j++) acc[i][j] += aa[i] * bb[j];
        }
    }

    // epilogue: normalize, zero invalid queries, write ctx in [t][Dm] layout
    #pragma unroll
    for (int i = 0; i < 8; i++) {
        int r = (i < 4) ? (ty * 4 + i) : (64 + ty * 4 + (i - 4));
        int q = q0 + r;
        float inv = g_mask[z * Nn + q] ? (1.0f / l_i[i]) : 0.0f;
        float4 o = make_float4(acc[i][0] * inv, acc[i][1] * inv,
                               acc[i][2] * inv, acc[i][3] * inv);
        *(float4*)&g_ctx[(size_t)(z * Nn + q) * DM + h * DKk + tx * 4] = o;
    }
}

// ---------------- output projection: out = ctx @ Wo^T ----------------
// 128x128 tile, BK=16, 8x8 split microtile.
__global__ __launch_bounds__(256) void outproj_kernel(
    const float* __restrict__ Wo, float* __restrict__ out)
{
    __shared__ __align__(16) float sA[16 * SApad];  // [k][token]
    __shared__ __align__(16) float sB[16 * SApad];  // [k][col]

    int tid = threadIdx.x, tx = tid & 15, ty = tid >> 4;
    int t0 = blockIdx.x * 128, c0 = blockIdx.y * 128;
    float acc[8][8] = {};

    for (int i0 = 0; i0 < DM; i0 += 16) {
        #pragma unroll
        for (int it = 0; it < 2; it++) {
            int idx = tid + it * 256;
            int t = idx >> 2, k4 = idx & 3;
            float4 v4 = *(const float4*)&g_ctx[(size_t)(t0 + t) * DM + i0 + k4 * 4];
            sA[(k4 * 4 + 0) * SApad + t] = v4.x;
            sA[(k4 * 4 + 1) * SApad + t] = v4.y;
            sA[(k4 * 4 + 2) * SApad + t] = v4.z;
            sA[(k4 * 4 + 3) * SApad + t] = v4.w;
        }
        #pragma unroll
        for (int it = 0; it < 2; it++) {
            int idx = tid + it * 256;
            int c = idx >> 2, k4 = idx & 3;
            float4 w4 = *(const float4*)&Wo[(size_t)(c0 + c) * DM + i0 + k4 * 4];
            sB[(k4 * 4 + 0) * SApad + c] = w4.x;
            sB[(k4 * 4 + 1) * SApad + c] = w4.y;
            sB[(k4 * 4 + 2) * SApad + c] = w4.z;
            sB[(k4 * 4 + 3) * SApad + c] = w4.w;
        }
        __syncthreads();
        #pragma unroll
        for (int kk = 0; kk < 16; kk++) {
            float4 a0 = *(float4*)&sA[kk * SApad + ty * 4];
            float4 a1 = *(float4*)&sA[kk * SApad + 64 + ty * 4];
            float4 b0 = *(float4*)&sB[kk * SApad + tx * 4];
            float4 b1 = *(float4*)&sB[kk * SApad + 64 + tx * 4];
            float aa[8] = {a0.x, a0.y, a0.z, a0.w, a1.x, a1.y, a1.z, a1.w};
            float bb[8] = {b0.x, b0.y, b0.z, b0.w, b1.x, b1.y, b1.z, b1.w};
            #pragma unroll
            for (int i = 0; i < 8; i++)
                #pragma unroll
                for (int j = 0; j < 8; j++) acc[i][j] += aa[i] * bb[j];
        }
        __syncthreads();
    }

    #pragma unroll
    for (int i = 0; i < 8; i++) {
        int r = (i < 4) ? (ty * 4 + i) : (64 + ty * 4 + (i - 4));
        float* orow = &out[(size_t)(t0 + r) * DM + c0];
        *(float4*)&orow[tx * 4] =
            make_float4(acc[i][0], acc[i][1], acc[i][2], acc[i][3]);
        *(float4*)&orow[64 + tx * 4] =
            make_float4(acc[i][4], acc[i][5], acc[i][6], acc[i][7]);
    }
}

// ---------------- launch ----------------
extern "C" void kernel_launch(void* const* d_in, const int* in_sizes, int n_in,
                              void* d_out, int out_size) {
    const float* x  = (const float*)d_in[0];
    const unsigned char* mraw = (const unsigned char*)d_in[1];
    const float* qp = (const float*)d_in[2];
    const float* kp = (const float*)d_in[3];
    const float* vp = (const float*)d_in[4];
    const float* qb = (const float*)d_in[5];
    const float* kb = (const float*)d_in[6];
    const float* vb = (const float*)d_in[7];
    const float* ow = (const float*)d_in[8];
    float* out = (float*)d_out;

    cudaFuncSetAttribute(attn_kernel,
                         cudaFuncAttributeMaxDynamicSharedMemorySize, ATTN_SMEM);

    mask_kernel<<<1, 256>>>(mraw);
    qkv_kernel<<<dim3(Tt / 128, 3 * Hh), 256>>>(x, qp, kp, vp, qb, kb, vb);
    attn_kernel<<<dim3(Nn / 128, Hh, Zb), 256, ATTN_SMEM>>>();
    outproj_kernel<<<dim3(Tt / 128, DM / 128), 256>>>(ow, out);
}